// round 8
// baseline (speedup 1.0000x reference)
#include <cuda_runtime.h>

#define Bb   8
#define HW   1024
#define Cc   512
#define C4   128

// ---------------- scratch (__device__ globals; rewritten each launch) --------
__device__ __align__(16) float g_partial[Bb][16][Cc];
__device__ __align__(16) float g_xsum[Bb][Cc];
__device__ __align__(16) float g_xr[Bb][Cc];
__device__ __align__(16) float g_ksum[Bb][Cc];
__device__ __align__(16) float g_wpart[16][Bb][Cc];
__device__ __align__(16) float g_upart[16][Bb][Cc];
__device__ float    g_dot[Bb][HW];
__device__ unsigned g_mnk[Bb];
__device__ unsigned g_mxk[Bb];
__device__ unsigned g_t1[Bb];     // N1 tickets (reset by winner)
__device__ unsigned g_t3[Bb];     // N3 tickets (reset by winner)

__device__ __forceinline__ unsigned enc(float f) {
    unsigned u = __float_as_uint(f);
    return (u & 0x80000000u) ? ~u : (u | 0x80000000u);
}
__device__ __forceinline__ float dec(unsigned k) {
    return (k & 0x80000000u) ? __uint_as_float(k ^ 0x80000000u)
                             : __uint_as_float(~k);
}

#define CLUSTER_SYNC_() do {                                           \
    asm volatile("barrier.cluster.arrive.aligned;" ::: "memory");      \
    asm volatile("barrier.cluster.wait.aligned;" ::: "memory");        \
} while (0)

// ========== N1: colsum partials + ticket-fused Xsum reduce ===================
__global__ void __launch_bounds__(512) k1_colsum(const float* __restrict__ x) {
    __shared__ __align__(16) float4 shP[4][C4];
    __shared__ int isLast;
    const int g = blockIdx.x, t = threadIdx.x;
    const int b = g >> 4, s = g & 15;
    const int c4 = t & 127, rs = t >> 7;

    if (g == 0 && t < Bb) { g_mnk[t] = 0xFFFFFFFFu; g_mxk[t] = 0u; }

    const float4* base = reinterpret_cast<const float4*>(x)
                       + ((size_t)(b * HW + s * 64 + rs * 16)) * C4 + c4;
    float4 acc = make_float4(0.f, 0.f, 0.f, 0.f);
#pragma unroll
    for (int p = 0; p < 16; ++p) {
        float4 v = base[(size_t)p * C4];
        acc.x += v.x; acc.y += v.y; acc.z += v.z; acc.w += v.w;
    }
    shP[rs][c4] = acc;
    __syncthreads();
    if (t < C4) {
        float4 a = shP[0][t], p1 = shP[1][t], p2 = shP[2][t], p3 = shP[3][t];
        a.x += p1.x + p2.x + p3.x;  a.y += p1.y + p2.y + p3.y;
        a.z += p1.z + p2.z + p3.z;  a.w += p1.w + p2.w + p3.w;
        reinterpret_cast<float4*>(g_partial[b][s])[t] = a;
    }
    __syncthreads();
    if (t == 0) {
        __threadfence();
        isLast = (atomicAdd(&g_t1[b], 1u) == 15u);
    }
    __syncthreads();
    if (isLast) {
        // fixed-order reduce of the 16 partials -> Xsum (deterministic)
        float a = 0.f;
#pragma unroll
        for (int sp = 0; sp < 16; ++sp) a += g_partial[b][sp][t];
        g_xsum[b][t] = a;
        if (t == 0) g_t1[b] = 0u;   // reset for next replay
    }
}

// ========== N2: whole mid-chain in one 8-block cluster =======================
__global__ void __launch_bounds__(1024, 1) __cluster_dims__(8, 1, 1)
k2_mid(const float* __restrict__ conv_w, const float* __restrict__ conv_b,
       const float* __restrict__ q_w,
       const float* __restrict__ k_w,    const float* __restrict__ k_b)
{
    __shared__ __align__(16) float shA[Bb][Cc];   // 16 KB, reused per stage
    __shared__ float shTot[Cc];
    __shared__ float shW2[Bb][64];
    float4* shA4 = reinterpret_cast<float4*>(shA);

    const int r    = blockIdx.x;          // cluster rank 0..7
    const int t    = threadIdx.x;         // 0..1023
    const int warp = t >> 5, lane = t & 31;
    const float4* cw4 = reinterpret_cast<const float4*>(conv_w);
    const float4* kw4 = reinterpret_cast<const float4*>(k_w);

    // ---- load Xsum into smem
    shA4[t] = reinterpret_cast<const float4*>(g_xsum)[t];
    __syncthreads();

    // ---- s1: xr = (conv_w+I) Xsum + HW*conv_b.  rows [r*64, r*64+64).
#pragma unroll
    for (int rr = 0; rr < 2; ++rr) {
        const int o = r * 64 + warp * 2 + rr;
        const float4* W4 = cw4 + (size_t)o * C4;
        float acc[Bb];
#pragma unroll
        for (int b = 0; b < Bb; ++b) acc[b] = 0.f;
#pragma unroll
        for (int k = 0; k < 4; ++k) {
            const int c4i = lane + 32 * k;
            const float4 wv = W4[c4i];
#pragma unroll
            for (int b = 0; b < Bb; ++b) {
                const float4 xa = shA4[b * C4 + c4i];
                acc[b] += wv.x * xa.x + wv.y * xa.y + wv.z * xa.z + wv.w * xa.w;
            }
        }
#pragma unroll
        for (int b = 0; b < Bb; ++b)
#pragma unroll
            for (int off = 16; off; off >>= 1)
                acc[b] += __shfl_xor_sync(0xffffffffu, acc[b], off);
        if (lane == 0) {
            const float cb = (float)HW * conv_b[o];
#pragma unroll
            for (int b = 0; b < Bb; ++b)
                g_xr[b][o] = acc[b] + cb + shA[b][o];
        }
    }
    __threadfence();
    CLUSTER_SYNC_();

    // ---- s2: Ksum = k_w xr + HW*k_b.  rows [r*64, +64).
    __syncthreads();
    shA4[t] = reinterpret_cast<const float4*>(g_xr)[t];
    __syncthreads();
#pragma unroll
    for (int rr = 0; rr < 2; ++rr) {
        const int o = r * 64 + warp * 2 + rr;
        const float4* W4 = kw4 + (size_t)o * C4;
        float acc[Bb];
#pragma unroll
        for (int b = 0; b < Bb; ++b) acc[b] = 0.f;
#pragma unroll
        for (int k = 0; k < 4; ++k) {
            const int c4i = lane + 32 * k;
            const float4 wv = W4[c4i];
#pragma unroll
            for (int b = 0; b < Bb; ++b) {
                const float4 xa = shA4[b * C4 + c4i];
                acc[b] += wv.x * xa.x + wv.y * xa.y + wv.z * xa.z + wv.w * xa.w;
            }
        }
#pragma unroll
        for (int b = 0; b < Bb; ++b)
#pragma unroll
            for (int off = 16; off; off >>= 1)
                acc[b] += __shfl_xor_sync(0xffffffffu, acc[b], off);
        if (lane == 0) {
            const float kb = (float)HW * k_b[o];
#pragma unroll
            for (int b = 0; b < Bb; ++b)
                g_ksum[b][o] = acc[b] + kb;
        }
    }
    __threadfence();
    CLUSTER_SYNC_();

    // ---- s3: v = KsumAll - Ksum (in smem); wpart over o-chunk [r*64, +64).
    __syncthreads();
    shA4[t] = reinterpret_cast<const float4*>(g_ksum)[t];
    __syncthreads();
    if (t < Cc) {
        float tot = 0.f;
#pragma unroll
        for (int b = 0; b < Bb; ++b) tot += shA[b][t];
        shTot[t] = tot;
    }
    __syncthreads();
#pragma unroll
    for (int i = 0; i < 4; ++i) {
        const int idx = t + i * 1024;
        const int b = idx >> 9, c = idx & 511;
        shA[b][c] = shTot[c] - shA[b][c];      // v in place
    }
    __syncthreads();
    {
        const int c = t & 511, h = t >> 9;      // h: which 32-o half
        const int ob = r * 64 + h * 32;
        float vreg[Bb];
#pragma unroll
        for (int b = 0; b < Bb; ++b) vreg[b] = shA[b][ob + lane];
        float acc[Bb];
#pragma unroll
        for (int b = 0; b < Bb; ++b) acc[b] = 0.f;
#pragma unroll
        for (int oo = 0; oo < 32; ++oo) {
            const float wv = q_w[(size_t)(ob + oo) * Cc + c];
#pragma unroll
            for (int b = 0; b < Bb; ++b)
                acc[b] += wv * __shfl_sync(0xffffffffu, vreg[b], oo);
        }
#pragma unroll
        for (int b = 0; b < Bb; ++b) g_wpart[r * 2 + h][b][c] = acc[b];
    }
    __threadfence();
    CLUSTER_SYNC_();

    // ---- s4: w at own o-chunk; upart = conv_w^T w over chunk (+w residual r==0)
    __syncthreads();
    if (t < Bb * 64) {                           // w[b][r*64+oi], fixed-order sum
        const int b = t >> 6, oi = t & 63;
        float a = 0.f;
#pragma unroll
        for (int sp = 0; sp < 16; ++sp) a += g_wpart[sp][b][r * 64 + oi];
        shW2[b][oi] = a;
    }
    if (r == 0) {                                // full w for the +w residual
#pragma unroll
        for (int i = 0; i < 4; ++i) {
            const int idx = t + i * 1024;
            const int b = idx >> 9, c = idx & 511;
            float a = 0.f;
#pragma unroll
            for (int sp = 0; sp < 16; ++sp) a += g_wpart[sp][b][c];
            shA[b][c] = a;
        }
    }
    __syncthreads();
    {
        const int c = t & 511, h = t >> 9;
        const int ob = r * 64 + h * 32;
        float vreg[Bb];
#pragma unroll
        for (int b = 0; b < Bb; ++b) vreg[b] = shW2[b][h * 32 + lane];
        float acc[Bb];
#pragma unroll
        for (int b = 0; b < Bb; ++b) acc[b] = 0.f;
#pragma unroll
        for (int oo = 0; oo < 32; ++oo) {
            const float wv = conv_w[(size_t)(ob + oo) * Cc + c];
#pragma unroll
            for (int b = 0; b < Bb; ++b)
                acc[b] += wv * __shfl_sync(0xffffffffu, vreg[b], oo);
        }
        if (r == 0 && h == 0) {                  // +w residual, exactly once per c
#pragma unroll
            for (int b = 0; b < Bb; ++b) acc[b] += shA[b][c];
        }
#pragma unroll
        for (int b = 0; b < Bb; ++b) g_upart[r * 2 + h][b][c] = acc[b];
    }
}

// ========== N3: u assemble + dot + minmax + ticket-fused epilogue ============
__global__ void __launch_bounds__(512) k3_dot(const float* __restrict__ x,
                                              float* __restrict__ out) {
    __shared__ float psum[64][C4];      // 32 KB
    __shared__ float shB[Cc];
    __shared__ float sdot[64];
    __shared__ int isLast;
    const int g = blockIdx.x, t = threadIdx.x;
    const int b = g >> 4, s = g & 15;
    const int warp = t >> 5, lane = t & 31;
    const int c4 = t & 127, rs = t >> 7;

    {   // u[t] = sum_j upart[j][b][t]   (residual already inside slot 0)
        float a = 0.f;
#pragma unroll
        for (int jj = 0; jj < 16; ++jj) a += g_upart[jj][b][t];
        shB[t] = a;
    }
    __syncthreads();

    const float4 uv = reinterpret_cast<const float4*>(shB)[c4];
    const float4* base = reinterpret_cast<const float4*>(x)
                       + ((size_t)(b * HW + s * 64 + rs * 16)) * C4 + c4;
#pragma unroll
    for (int p = 0; p < 16; ++p) {
        const float4 xv = base[(size_t)p * C4];
        psum[rs * 16 + p][c4] = xv.x * uv.x + xv.y * uv.y + xv.z * uv.z + xv.w * uv.w;
    }
    __syncthreads();

#pragma unroll
    for (int rr = 0; rr < 4; ++rr) {
        const int row = warp * 4 + rr;
        float sm = psum[row][lane] + psum[row][lane + 32]
                 + psum[row][lane + 64] + psum[row][lane + 96];
#pragma unroll
        for (int off = 16; off; off >>= 1)
            sm += __shfl_xor_sync(0xffffffffu, sm, off);
        if (lane == 0) { sdot[row] = sm; g_dot[b][s * 64 + row] = sm; }
    }
    __syncthreads();
    if (warp == 0) {
        float v0 = sdot[lane], v1 = sdot[lane + 32];
        float mn = fminf(v0, v1), mx = fmaxf(v0, v1);
#pragma unroll
        for (int off = 16; off; off >>= 1) {
            mn = fminf(mn, __shfl_xor_sync(0xffffffffu, mn, off));
            mx = fmaxf(mx, __shfl_xor_sync(0xffffffffu, mx, off));
        }
        if (lane == 0) {
            atomicMin(&g_mnk[b], enc(mn));
            atomicMax(&g_mxk[b], enc(mx));
        }
    }
    __syncthreads();
    if (t == 0) {
        __threadfence();
        isLast = (atomicAdd(&g_t3[b], 1u) == 15u);
    }
    __syncthreads();
    if (isLast) {
        const float mn = dec(g_mnk[b]);
        const float mx = dec(g_mxk[b]);
        const float inv = 1.0f / (mx - mn);
#pragma unroll
        for (int i = 0; i < 2; ++i) {
            const int idx = t + i * 512;
            const float z = ((g_dot[b][idx] - mn) * inv - 0.65f) / 0.15f;
            out[b * HW + idx] = 1.0f / (1.0f + __expf(-z));
        }
        if (t == 0) g_t3[b] = 0u;   // reset for next replay
    }
}

// ---------------------------------------------------------------------------
extern "C" void kernel_launch(void* const* d_in, const int* in_sizes, int n_in,
                              void* d_out, int out_size) {
    const float* x      = (const float*)d_in[0];
    const float* conv_w = (const float*)d_in[1];
    const float* conv_b = (const float*)d_in[2];
    const float* q_w    = (const float*)d_in[3];
    // d_in[4] = q_b: per-batch constant, cancels in min/max normalization.
    const float* k_w    = (const float*)d_in[5];
    const float* k_b    = (const float*)d_in[6];
    float* out = (float*)d_out;

    k1_colsum<<<128, 512>>>(x);
    k2_mid   <<<  8, 1024>>>(conv_w, conv_b, q_w, k_w, k_b);
    k3_dot   <<<128, 512>>>(x, out);
}

// round 9
// speedup vs baseline: 1.6841x; 1.6841x over previous
#include <cuda_runtime.h>

#define Bb   8
#define HW   1024
#define Cc   512
#define C4   128
#define NBLK 128
#define NTHR 512
#define DYN_BYTES (64 * 1024 + 32 * 1024)   // wbuf 64KB + psum 32KB

// ---------------- sync counters, one per 128-B line ---------------------------
struct alignas(128) Line { unsigned v; unsigned pad[31]; };
__device__ Line c_colsum[8];   // per-batch colsum tickets (16 each)
__device__ Line c_xsum;        // xsum winners (8)
__device__ Line c_xr[4];       // xr arrivals (64, 16/line)
__device__ Line c_ksum[4];     // ksum arrivals (64, 16/line)
__device__ Line c_wp;          // wpart tickets (16)
__device__ Line c_wready;      // w ready (1)
__device__ Line c_up;          // upart arrivals (16)
__device__ Line c_ep[8];       // per-batch epilogue tickets (16 each)
__device__ Line c_fin;         // 8 winners; 8th resets all
__device__ unsigned g_mnk[Bb];
__device__ unsigned g_mxk[Bb];

// ---------------- data scratch (fully rewritten every launch) -----------------
__device__ __align__(16) float4 g_partial4[Bb][16][C4];
__device__ __align__(16) float  g_xsum[Bb][Cc];
__device__ __align__(16) float  g_xr[Bb][Cc];
__device__ __align__(16) float  g_ksum[Bb][Cc];
__device__ __align__(16) float  g_wpart[16][Bb][Cc];
__device__ __align__(16) float  g_w[Bb][Cc];
__device__ __align__(16) float  g_upart[16][Bb][Cc];
__device__ float g_dot[Bb][HW];

__device__ __forceinline__ unsigned ld_acq(const unsigned* p) {
    unsigned v;
    asm volatile("ld.acquire.gpu.global.u32 %0, [%1];" : "=r"(v) : "l"(p) : "memory");
    return v;
}
__device__ __forceinline__ unsigned atom_add(unsigned* p, unsigned v) {
    unsigned o;
    asm volatile("atom.relaxed.gpu.global.add.u32 %0, [%1], %2;"
                 : "=r"(o) : "l"(p), "r"(v) : "memory");
    return o;
}
__device__ __forceinline__ unsigned enc(float f) {
    unsigned u = __float_as_uint(f);
    return (u & 0x80000000u) ? ~u : (u | 0x80000000u);
}
__device__ __forceinline__ float dec(unsigned k) {
    return (k & 0x80000000u) ? __uint_as_float(k ^ 0x80000000u)
                             : __uint_as_float(~k);
}

// producers: fence by all threads, then t0 bumps (relaxed is enough post-fence)
#define ARRIVE(lineptr)                                               \
    do { __threadfence(); __syncthreads();                            \
         if (t == 0) atom_add(&(lineptr)->v, 1u);                     \
    } while (0)
// waits: t0 polls n lines with parallel acquire loads, then block sync
#define WAITGE(arr, n, tgt)                                           \
    do { if (t == 0) {                                                \
             unsigned s_;                                             \
             do { s_ = 0;                                             \
                  _Pragma("unroll")                                   \
                  for (int i_ = 0; i_ < (n); ++i_) s_ += ld_acq(&(arr)[i_].v); \
             } while (s_ < (unsigned)(tgt));                          \
         }                                                            \
         __syncthreads();                                             \
    } while (0)
// ticket: fence+bump, broadcast old value through smem
#define TICKET(lineptr, shvar)                                        \
    do { __threadfence(); __syncthreads();                            \
         if (t == 0) (shvar) = atom_add(&(lineptr)->v, 1u);           \
         __syncthreads();                                             \
    } while (0)

__global__ void __launch_bounds__(NTHR)
fused_kernel(const float* __restrict__ x,
             const float* __restrict__ conv_w, const float* __restrict__ conv_b,
             const float* __restrict__ q_w,
             const float* __restrict__ k_w,    const float* __restrict__ k_b,
             float* __restrict__ out)
{
    extern __shared__ float dynsh[];
    float*  wbuf  = dynsh;                                  // 16384 f (64 KB)
    float4* wbuf4 = reinterpret_cast<float4*>(dynsh);
    float*  psum  = dynsh + 16384;                          // 8192 f (32 KB)
    __shared__ __align__(16) float shA[Bb][Cc];             // 16 KB
    __shared__ __align__(16) float shB[Cc];                 // 2 KB
    __shared__ float s_part[16][Bb];
    __shared__ float shW[Bb][32];
    __shared__ float sdot[64];
    __shared__ unsigned sh_tk;
    float4* shA4 = reinterpret_cast<float4*>(shA);

    const int g    = blockIdx.x;
    const int t    = threadIdx.x;
    const int warp = t >> 5, lane = t & 31;
    const int b_own = g >> 4, s_own = g & 15;
    const int c4t = t & 127, rs = t >> 7;

    // ============ P1: x tile -> registers (+colsum) & weight prefetch ========
    float4 xreg[16];
    {
        if (g == 0 && t < Bb) { g_mnk[t] = 0xFFFFFFFFu; g_mxk[t] = 0u; }

        const float4* base = reinterpret_cast<const float4*>(x)
                           + ((size_t)(b_own * HW + s_own * 64 + rs * 16)) * C4 + c4t;
        float4 acc = make_float4(0.f, 0.f, 0.f, 0.f);
#pragma unroll
        for (int p = 0; p < 16; ++p) {
            xreg[p] = base[(size_t)p * C4];
            acc.x += xreg[p].x; acc.y += xreg[p].y;
            acc.z += xreg[p].z; acc.w += xreg[p].w;
        }
        shA4[rs * C4 + c4t] = acc;

        // weight prefetch (overlaps x loads)
        if (g >= 64) {                      // W: conv rows (g-64)*8 + k_w rows
            const float4* s1 = reinterpret_cast<const float4*>(conv_w) + (g - 64) * 1024;
            const float4* s2 = reinterpret_cast<const float4*>(k_w)    + (g - 64) * 1024;
#pragma unroll
            for (int i = 0; i < 2; ++i) wbuf4[t + i * NTHR]        = s1[t + i * NTHR];
#pragma unroll
            for (int i = 0; i < 2; ++i) wbuf4[1024 + t + i * NTHR] = s2[t + i * NTHR];
        } else if (g < 16) {                // C: q_w rows [g*32, +32)
            const float4* src = reinterpret_cast<const float4*>(q_w) + g * 4096;
#pragma unroll
            for (int i = 0; i < 8; ++i) wbuf4[t + i * NTHR] = src[t + i * NTHR];
        } else if (g < 32) {                // D: conv_w rows [(g-16)*32, +32)
            const float4* src = reinterpret_cast<const float4*>(conv_w) + (g - 16) * 4096;
#pragma unroll
            for (int i = 0; i < 8; ++i) wbuf4[t + i * NTHR] = src[t + i * NTHR];
        }
        __syncthreads();
        if (t < C4) {
            float4 a = shA4[t], p1 = shA4[C4 + t], p2 = shA4[2 * C4 + t], p3 = shA4[3 * C4 + t];
            a.x += p1.x + p2.x + p3.x;  a.y += p1.y + p2.y + p3.y;
            a.z += p1.z + p2.z + p3.z;  a.w += p1.w + p2.w + p3.w;
            g_partial4[b_own][s_own][t] = a;
        }
    }
    // colsum ticket: last block per batch reduces Xsum (fixed order, deterministic)
    TICKET(&c_colsum[b_own], sh_tk);
    if (sh_tk == 15u) {
        __threadfence();   // acquire: see other blocks' partials
        const float* gp = &g_partial4[0][0][0].x;
        float a = 0.f;
#pragma unroll
        for (int sp = 0; sp < 16; ++sp)
            a += gp[(b_own * 16 + sp) * Cc + t];
        g_xsum[b_own][t] = a;
        __threadfence(); __syncthreads();
        if (t == 0) atom_add(&c_xsum.v, 1u);
    }

    // ============ W blocks (64..127): xr matvec, then Ksum matvec ============
    if (g >= 64) {
        const int a = g - 64;               // rows [a*8, a*8+8)
        WAITGE(&c_xsum, 1, 8);
#pragma unroll
        for (int i = 0; i < 2; ++i)
            shA4[t + i * NTHR] = reinterpret_cast<const float4*>(g_xsum)[t + i * NTHR];
        __syncthreads();
        {   // xr = (conv_w+I) Xsum + HW*conv_b; 2 warps/row
            const int rowL = warp >> 1, h = warp & 1;
            float acc[Bb];
#pragma unroll
            for (int b = 0; b < Bb; ++b) acc[b] = 0.f;
#pragma unroll
            for (int k = 0; k < 2; ++k) {
                const int c4 = h * 64 + k * 32 + lane;
                const float4 wv = wbuf4[rowL * C4 + c4];
#pragma unroll
                for (int b = 0; b < Bb; ++b) {
                    const float4 xa = shA4[b * C4 + c4];
                    acc[b] += wv.x * xa.x + wv.y * xa.y + wv.z * xa.z + wv.w * xa.w;
                }
            }
#pragma unroll
            for (int b = 0; b < Bb; ++b)
#pragma unroll
                for (int off = 16; off; off >>= 1)
                    acc[b] += __shfl_xor_sync(0xffffffffu, acc[b], off);
            if (lane == 0)
#pragma unroll
                for (int b = 0; b < Bb; ++b) s_part[warp][b] = acc[b];
        }
        __syncthreads();
        if (t < 64) {
            const int rL = t >> 3, b = t & 7;
            const int o = a * 8 + rL;
            g_xr[b][o] = s_part[rL * 2][b] + s_part[rL * 2 + 1][b]
                       + (float)HW * conv_b[o] + shA[b][o];
        }
        ARRIVE(&c_xr[a & 3]);
        WAITGE(c_xr, 4, 64);

#pragma unroll
        for (int i = 0; i < 2; ++i)
            shA4[t + i * NTHR] = reinterpret_cast<const float4*>(g_xr)[t + i * NTHR];
        __syncthreads();
        {   // Ksum = k_w xr + HW*k_b
            const int rowL = warp >> 1, h = warp & 1;
            float acc[Bb];
#pragma unroll
            for (int b = 0; b < Bb; ++b) acc[b] = 0.f;
#pragma unroll
            for (int k = 0; k < 2; ++k) {
                const int c4 = h * 64 + k * 32 + lane;
                const float4 wv = wbuf4[1024 + rowL * C4 + c4];
#pragma unroll
                for (int b = 0; b < Bb; ++b) {
                    const float4 xa = shA4[b * C4 + c4];
                    acc[b] += wv.x * xa.x + wv.y * xa.y + wv.z * xa.z + wv.w * xa.w;
                }
            }
#pragma unroll
            for (int b = 0; b < Bb; ++b)
#pragma unroll
                for (int off = 16; off; off >>= 1)
                    acc[b] += __shfl_xor_sync(0xffffffffu, acc[b], off);
            if (lane == 0)
#pragma unroll
                for (int b = 0; b < Bb; ++b) s_part[warp][b] = acc[b];
        }
        __syncthreads();
        if (t < 64) {
            const int rL = t >> 3, b = t & 7;
            const int o = a * 8 + rL;
            g_ksum[b][o] = s_part[rL * 2][b] + s_part[rL * 2 + 1][b]
                         + (float)HW * k_b[o];
        }
        ARRIVE(&c_ksum[a & 3]);
    }

    // ============ C blocks (0..15): v + wpart; winner reduces w ==============
    if (g < 16) {
        WAITGE(c_ksum, 4, 64);
#pragma unroll
        for (int i = 0; i < 2; ++i)
            shA4[t + i * NTHR] = reinterpret_cast<const float4*>(g_ksum)[t + i * NTHR];
        __syncthreads();
        float tot = 0.f;
#pragma unroll
        for (int b = 0; b < Bb; ++b) tot += shA[b][t];
        shB[t] = tot;
        __syncthreads();
#pragma unroll
        for (int b = 0; b < Bb; ++b) shA[b][t] = shB[t] - shA[b][t];   // v in place
        __syncthreads();

        float vreg[Bb];
#pragma unroll
        for (int b = 0; b < Bb; ++b) vreg[b] = shA[b][g * 32 + lane];
        float acc[Bb];
#pragma unroll
        for (int b = 0; b < Bb; ++b) acc[b] = 0.f;
#pragma unroll
        for (int oo = 0; oo < 32; ++oo) {
            const float wv = wbuf[oo * Cc + t];
#pragma unroll
            for (int b = 0; b < Bb; ++b)
                acc[b] += wv * __shfl_sync(0xffffffffu, vreg[b], oo);
        }
#pragma unroll
        for (int b = 0; b < Bb; ++b) g_wpart[g][b][t] = acc[b];

        TICKET(&c_wp, sh_tk);
        if (sh_tk == 15u) {                 // winner reduces w (fixed order)
            __threadfence();
#pragma unroll
            for (int b = 0; b < Bb; ++b) {
                float a = 0.f;
#pragma unroll
                for (int jj = 0; jj < 16; ++jj) a += g_wpart[jj][b][t];
                g_w[b][t] = a;
            }
            __threadfence(); __syncthreads();
            if (t == 0) atom_add(&c_wready.v, 1u);
        }
    }

    // ============ D blocks (16..31): upart over own o-chunk ==================
    if (g >= 16 && g < 32) {
        const int j = g - 16;
        WAITGE(&c_wready, 1, 1);
        if (t < 256) shW[t >> 5][t & 31] = g_w[t >> 5][j * 32 + (t & 31)];
        __syncthreads();

        float vreg[Bb];
#pragma unroll
        for (int b = 0; b < Bb; ++b) vreg[b] = shW[b][lane];
        float acc[Bb];
#pragma unroll
        for (int b = 0; b < Bb; ++b) acc[b] = 0.f;
#pragma unroll
        for (int oo = 0; oo < 32; ++oo) {
            const float wv = wbuf[oo * Cc + t];
#pragma unroll
            for (int b = 0; b < Bb; ++b)
                acc[b] += wv * __shfl_sync(0xffffffffu, vreg[b], oo);
        }
#pragma unroll
        for (int b = 0; b < Bb; ++b) g_upart[j][b][t] = acc[b];
        ARRIVE(&c_up);
    }

    // ============ all blocks: u assemble + dot + epilogue ====================
    WAITGE(&c_up, 1, 16);
    {
        float a = g_w[b_own][t];            // +w residual
#pragma unroll
        for (int jj = 0; jj < 16; ++jj) a += g_upart[jj][b_own][t];
        shB[t] = a;
        __syncthreads();

        const float4 uv = reinterpret_cast<const float4*>(shB)[c4t];
#pragma unroll
        for (int p = 0; p < 16; ++p) {
            const float4 xv = xreg[p];
            psum[(rs * 16 + p) * C4 + c4t] =
                xv.x * uv.x + xv.y * uv.y + xv.z * uv.z + xv.w * uv.w;
        }
        __syncthreads();
#pragma unroll
        for (int rr = 0; rr < 4; ++rr) {
            const int row = warp * 4 + rr;
            float sm = psum[row * C4 + lane] + psum[row * C4 + lane + 32]
                     + psum[row * C4 + lane + 64] + psum[row * C4 + lane + 96];
#pragma unroll
            for (int off = 16; off; off >>= 1)
                sm += __shfl_xor_sync(0xffffffffu, sm, off);
            if (lane == 0) { sdot[row] = sm; g_dot[b_own][s_own * 64 + row] = sm; }
        }
    }
    __syncthreads();
    if (warp == 0) {
        float v0 = sdot[lane], v1 = sdot[lane + 32];
        float mn = fminf(v0, v1), mx = fmaxf(v0, v1);
#pragma unroll
        for (int off = 16; off; off >>= 1) {
            mn = fminf(mn, __shfl_xor_sync(0xffffffffu, mn, off));
            mx = fmaxf(mx, __shfl_xor_sync(0xffffffffu, mx, off));
        }
        if (lane == 0) {
            atomicMin(&g_mnk[b_own], enc(mn));
            atomicMax(&g_mxk[b_own], enc(mx));
        }
    }
    TICKET(&c_ep[b_own], sh_tk);
    if (sh_tk == 15u) {                     // per-batch winner writes outputs
        __threadfence();
        const float mn = dec(g_mnk[b_own]);
        const float mx = dec(g_mxk[b_own]);
        const float inv = 1.0f / (mx - mn);
#pragma unroll
        for (int i = 0; i < 2; ++i) {
            const int idx = t + i * NTHR;
            const float z = ((g_dot[b_own][idx] - mn) * inv - 0.65f) / 0.15f;
            out[b_own * HW + idx] = 1.0f / (1.0f + __expf(-z));
        }
        __syncthreads();
        if (t == 0) {
            c_ep[b_own].v = 0u;             // reset own ticket
            __threadfence();
            unsigned old = atom_add(&c_fin.v, 1u);
            if (old == 7u) {                // 8th winner: reset everything
#pragma unroll
                for (int i = 0; i < 8; ++i) c_colsum[i].v = 0u;
#pragma unroll
                for (int i = 0; i < 4; ++i) { c_xr[i].v = 0u; c_ksum[i].v = 0u; }
                c_xsum.v = 0u; c_wp.v = 0u; c_wready.v = 0u; c_up.v = 0u;
                c_fin.v = 0u;
                __threadfence();
            }
        }
    }
}

// ---------------------------------------------------------------------------
extern "C" void kernel_launch(void* const* d_in, const int* in_sizes, int n_in,
                              void* d_out, int out_size) {
    const float* x      = (const float*)d_in[0];
    const float* conv_w = (const float*)d_in[1];
    const float* conv_b = (const float*)d_in[2];
    const float* q_w    = (const float*)d_in[3];
    // d_in[4] = q_b: per-batch constant, cancels in min/max normalization.
    const float* k_w    = (const float*)d_in[5];
    const float* k_b    = (const float*)d_in[6];
    float* out = (float*)d_out;

    cudaFuncSetAttribute(fused_kernel,
                         cudaFuncAttributeMaxDynamicSharedMemorySize,
                         DYN_BYTES);
    fused_kernel<<<NBLK, NTHR, DYN_BYTES>>>(x, conv_w, conv_b, q_w, k_w, k_b, out);
}

// round 10
// speedup vs baseline: 2.0538x; 1.2195x over previous
#include <cuda_runtime.h>

#define Bb   8
#define HW   1024
#define Cc   512
#define C4   128
#define NBLK 128
#define NTHR 512
#define DYN_BYTES (64 * 1024)   // wbuf 64KB

// ---------------- sync counters, one per 128-B line ---------------------------
struct alignas(128) Line { unsigned v; unsigned pad[31]; };
__device__ Line c_cs[8];    // colsum tickets per batch (16 each)
__device__ Line c_xs;       // xsum winners (8)
__device__ Line c_xr[4];    // xr arrivals (64, 16/line)
__device__ Line c_ks[4];    // ksum arrivals (64, 16/line)
__device__ Line c_wp;       // wpart arrivals (16)
__device__ Line c_up;       // upart arrivals (16)
__device__ Line c_ep[8];    // epilogue tickets per batch (16 each)
__device__ Line c_fin;      // 8 winners; 8th resets all
__device__ unsigned g_mnk[Bb] = {0xFFFFFFFFu,0xFFFFFFFFu,0xFFFFFFFFu,0xFFFFFFFFu,
                                 0xFFFFFFFFu,0xFFFFFFFFu,0xFFFFFFFFu,0xFFFFFFFFu};
__device__ unsigned g_mxk[Bb] = {0,0,0,0,0,0,0,0};

// ---------------- data scratch (fully rewritten every launch) -----------------
__device__ __align__(16) float4 g_partial4[Bb][16][C4];
__device__ __align__(16) float  g_xsum[Bb][Cc];
__device__ __align__(16) float  g_xr[Bb][Cc];
__device__ __align__(16) float  g_ksum[Bb][Cc];
__device__ __align__(16) float  g_wpart[16][Bb][Cc];
__device__ __align__(16) float  g_w[Bb][Cc];
__device__ __align__(16) float  g_upart[16][Bb][Cc];
__device__ float g_dot[Bb][HW];

__device__ __forceinline__ unsigned enc(float f) {
    unsigned u = __float_as_uint(f);
    return (u & 0x80000000u) ? ~u : (u | 0x80000000u);
}
__device__ __forceinline__ float dec(unsigned k) {
    return (k & 0x80000000u) ? __uint_as_float(k ^ 0x80000000u)
                             : __uint_as_float(~k);
}

// R5-proven primitives: volatile polls, plain atomics
#define ARRIVE(lineptr)                                               \
    do { __syncthreads();                                             \
         if (t == 0) { __threadfence(); atomicAdd(&(lineptr)->v, 1u); } \
    } while (0)
#define WAITGE(arr, n, tgt)                                           \
    do { if (t == 0) {                                                \
             unsigned s_;                                             \
             do { s_ = 0;                                             \
                  _Pragma("unroll")                                   \
                  for (int i_ = 0; i_ < (n); ++i_)                    \
                      s_ += *(volatile const unsigned*)&(arr)[i_].v;  \
             } while (s_ < (unsigned)(tgt));                          \
             __threadfence();                                         \
         }                                                            \
         __syncthreads();                                             \
    } while (0)

__global__ void __launch_bounds__(NTHR)
fused_kernel(const float* __restrict__ x,
             const float* __restrict__ conv_w, const float* __restrict__ conv_b,
             const float* __restrict__ q_w,
             const float* __restrict__ k_w,    const float* __restrict__ k_b,
             float* __restrict__ out)
{
    extern __shared__ float dynsh[];
    float*  wbuf  = dynsh;                                  // 16384 f (64 KB)
    float4* wbuf4 = reinterpret_cast<float4*>(dynsh);
    __shared__ __align__(16) float shA[Bb][Cc];             // 16 KB
    __shared__ __align__(16) float shB[Cc];                 // 2 KB
    __shared__ __align__(16) float psum[64][C4];            // 32 KB
    __shared__ float s_part[16][Bb];
    __shared__ float shW[Bb][32];
    __shared__ float sdot[64];
    __shared__ unsigned sh_tk;
    float4* shA4 = reinterpret_cast<float4*>(shA);

    const int g    = blockIdx.x;
    const int t    = threadIdx.x;
    const int warp = t >> 5, lane = t & 31;
    const int b_own = g >> 4, s_own = g & 15;
    const int c4t = t & 127, rs = t >> 7;

    // ============ P1: x tile -> registers (+colsum) & weight prefetch ========
    float4 xreg[16];
    {
        const float4* base = reinterpret_cast<const float4*>(x)
                           + ((size_t)(b_own * HW + s_own * 64 + rs * 16)) * C4 + c4t;
        float4 acc = make_float4(0.f, 0.f, 0.f, 0.f);
#pragma unroll
        for (int p = 0; p < 16; ++p) {
            xreg[p] = base[(size_t)p * C4];
            acc.x += xreg[p].x; acc.y += xreg[p].y;
            acc.z += xreg[p].z; acc.w += xreg[p].w;
        }
        shA4[rs * C4 + c4t] = acc;

        // weight prefetch (overlaps x loads)
        if (g >= 64) {                      // W: conv rows (g-64)*8 + k_w rows
            const float4* s1 = reinterpret_cast<const float4*>(conv_w) + (g - 64) * 1024;
            const float4* s2 = reinterpret_cast<const float4*>(k_w)    + (g - 64) * 1024;
#pragma unroll
            for (int i = 0; i < 2; ++i) wbuf4[t + i * NTHR]        = s1[t + i * NTHR];
#pragma unroll
            for (int i = 0; i < 2; ++i) wbuf4[1024 + t + i * NTHR] = s2[t + i * NTHR];
        } else if (g < 16) {                // C: q_w rows [g*32, +32)
            const float4* src = reinterpret_cast<const float4*>(q_w) + g * 4096;
#pragma unroll
            for (int i = 0; i < 8; ++i) wbuf4[t + i * NTHR] = src[t + i * NTHR];
        } else if (g < 32) {                // D: conv_w rows [(g-16)*32, +32)
            const float4* src = reinterpret_cast<const float4*>(conv_w) + (g - 16) * 4096;
#pragma unroll
            for (int i = 0; i < 8; ++i) wbuf4[t + i * NTHR] = src[t + i * NTHR];
        }
        __syncthreads();
        if (t < C4) {
            float4 a = shA4[t], p1 = shA4[C4 + t], p2 = shA4[2 * C4 + t], p3 = shA4[3 * C4 + t];
            a.x += p1.x + p2.x + p3.x;  a.y += p1.y + p2.y + p3.y;
            a.z += p1.z + p2.z + p3.z;  a.w += p1.w + p2.w + p3.w;
            g_partial4[b_own][s_own][t] = a;
        }
    }
    // colsum ticket: 16th block of each batch reduces Xsum (fixed order)
    __syncthreads();
    if (t == 0) { __threadfence(); sh_tk = atomicAdd(&c_cs[b_own].v, 1u); }
    __syncthreads();
    if (sh_tk == 15u) {
        __threadfence();                    // see other blocks' partials
        const float* gp = &g_partial4[0][0][0].x;
        float a = 0.f;
#pragma unroll
        for (int sp = 0; sp < 16; ++sp)
            a += gp[(b_own * 16 + sp) * Cc + t];
        g_xsum[b_own][t] = a;
        __syncthreads();
        if (t == 0) { __threadfence(); atomicAdd(&c_xs.v, 1u); }
    }

    // ============ W blocks (64..127): xr matvec, then Ksum matvec ============
    if (g >= 64) {
        const int a = g - 64;               // rows [a*8, a*8+8)
        WAITGE(&c_xs, 1, 8);
#pragma unroll
        for (int i = 0; i < 2; ++i)
            shA4[t + i * NTHR] = reinterpret_cast<const float4*>(g_xsum)[t + i * NTHR];
        __syncthreads();
        {   // xr = (conv_w+I) Xsum + HW*conv_b; 2 warps/row
            const int rowL = warp >> 1, h = warp & 1;
            float acc[Bb];
#pragma unroll
            for (int b = 0; b < Bb; ++b) acc[b] = 0.f;
#pragma unroll
            for (int k = 0; k < 2; ++k) {
                const int c4 = h * 64 + k * 32 + lane;
                const float4 wv = wbuf4[rowL * C4 + c4];
#pragma unroll
                for (int b = 0; b < Bb; ++b) {
                    const float4 xa = shA4[b * C4 + c4];
                    acc[b] += wv.x * xa.x + wv.y * xa.y + wv.z * xa.z + wv.w * xa.w;
                }
            }
#pragma unroll
            for (int b = 0; b < Bb; ++b)
#pragma unroll
                for (int off = 16; off; off >>= 1)
                    acc[b] += __shfl_xor_sync(0xffffffffu, acc[b], off);
            if (lane == 0)
#pragma unroll
                for (int b = 0; b < Bb; ++b) s_part[warp][b] = acc[b];
        }
        __syncthreads();
        if (t < 64) {
            const int rL = t >> 3, b = t & 7;
            const int o = a * 8 + rL;
            g_xr[b][o] = s_part[rL * 2][b] + s_part[rL * 2 + 1][b]
                       + (float)HW * conv_b[o] + shA[b][o];
        }
        ARRIVE(&c_xr[a & 3]);
        WAITGE(c_xr, 4, 64);

#pragma unroll
        for (int i = 0; i < 2; ++i)
            shA4[t + i * NTHR] = reinterpret_cast<const float4*>(g_xr)[t + i * NTHR];
        __syncthreads();
        {   // Ksum = k_w xr + HW*k_b
            const int rowL = warp >> 1, h = warp & 1;
            float acc[Bb];
#pragma unroll
            for (int b = 0; b < Bb; ++b) acc[b] = 0.f;
#pragma unroll
            for (int k = 0; k < 2; ++k) {
                const int c4 = h * 64 + k * 32 + lane;
                const float4 wv = wbuf4[1024 + rowL * C4 + c4];
#pragma unroll
                for (int b = 0; b < Bb; ++b) {
                    const float4 xa = shA4[b * C4 + c4];
                    acc[b] += wv.x * xa.x + wv.y * xa.y + wv.z * xa.z + wv.w * xa.w;
                }
            }
#pragma unroll
            for (int b = 0; b < Bb; ++b)
#pragma unroll
                for (int off = 16; off; off >>= 1)
                    acc[b] += __shfl_xor_sync(0xffffffffu, acc[b], off);
            if (lane == 0)
#pragma unroll
                for (int b = 0; b < Bb; ++b) s_part[warp][b] = acc[b];
        }
        __syncthreads();
        if (t < 64) {
            const int rL = t >> 3, b = t & 7;
            const int o = a * 8 + rL;
            g_ksum[b][o] = s_part[rL * 2][b] + s_part[rL * 2 + 1][b]
                         + (float)HW * k_b[o];
        }
        ARRIVE(&c_ks[a & 3]);
    }

    // ============ C blocks (0..15): v + wpart over own o-chunk ===============
    if (g < 16) {
        WAITGE(c_ks, 4, 64);
#pragma unroll
        for (int i = 0; i < 2; ++i)
            shA4[t + i * NTHR] = reinterpret_cast<const float4*>(g_ksum)[t + i * NTHR];
        __syncthreads();
        float tot = 0.f;
#pragma unroll
        for (int b = 0; b < Bb; ++b) tot += shA[b][t];
        shB[t] = tot;
        __syncthreads();
#pragma unroll
        for (int b = 0; b < Bb; ++b) shA[b][t] = shB[t] - shA[b][t];   // v in place
        __syncthreads();

        float vreg[Bb];
#pragma unroll
        for (int b = 0; b < Bb; ++b) vreg[b] = shA[b][g * 32 + lane];
        float acc[Bb];
#pragma unroll
        for (int b = 0; b < Bb; ++b) acc[b] = 0.f;
#pragma unroll
        for (int oo = 0; oo < 32; ++oo) {
            const float wv = wbuf[oo * Cc + t];
#pragma unroll
            for (int b = 0; b < Bb; ++b)
                acc[b] += wv * __shfl_sync(0xffffffffu, vreg[b], oo);
        }
#pragma unroll
        for (int b = 0; b < Bb; ++b) g_wpart[g][b][t] = acc[b];
        ARRIVE(&c_wp);
    }

    // ============ D blocks (16..31): inline w reduce + upart =================
    if (g >= 16 && g < 32) {
        const int j = g - 16;
        WAITGE(&c_wp, 1, 16);
        if (t < 256) {                      // w for own o-chunk, fixed order
            const int b = t >> 5, oo = t & 31;
            float s = 0.f;
#pragma unroll
            for (int jj = 0; jj < 16; ++jj) s += g_wpart[jj][b][j * 32 + oo];
            shW[b][oo] = s;
            g_w[b][j * 32 + oo] = s;        // +w residual source for dot phase
        }
        __syncthreads();

        float vreg[Bb];
#pragma unroll
        for (int b = 0; b < Bb; ++b) vreg[b] = shW[b][lane];
        float acc[Bb];
#pragma unroll
        for (int b = 0; b < Bb; ++b) acc[b] = 0.f;
#pragma unroll
        for (int oo = 0; oo < 32; ++oo) {
            const float wv = wbuf[oo * Cc + t];
#pragma unroll
            for (int b = 0; b < Bb; ++b)
                acc[b] += wv * __shfl_sync(0xffffffffu, vreg[b], oo);
        }
#pragma unroll
        for (int b = 0; b < Bb; ++b) g_upart[j][b][t] = acc[b];
        ARRIVE(&c_up);
    }

    // ============ all blocks: u assemble + dot + epilogue ====================
    WAITGE(&c_up, 1, 16);
    {
        float a = g_w[b_own][t];            // +w residual
#pragma unroll
        for (int jj = 0; jj < 16; ++jj) a += g_upart[jj][b_own][t];
        shB[t] = a;
        __syncthreads();

        const float4 uv = reinterpret_cast<const float4*>(shB)[c4t];
#pragma unroll
        for (int p = 0; p < 16; ++p) {
            const float4 xv = xreg[p];
            psum[rs * 16 + p][c4t] =
                xv.x * uv.x + xv.y * uv.y + xv.z * uv.z + xv.w * uv.w;
        }
        __syncthreads();
#pragma unroll
        for (int rr = 0; rr < 4; ++rr) {
            const int row = warp * 4 + rr;
            float sm = psum[row][lane] + psum[row][lane + 32]
                     + psum[row][lane + 64] + psum[row][lane + 96];
#pragma unroll
            for (int off = 16; off; off >>= 1)
                sm += __shfl_xor_sync(0xffffffffu, sm, off);
            if (lane == 0) { sdot[row] = sm; g_dot[b_own][s_own * 64 + row] = sm; }
        }
    }
    __syncthreads();
    if (warp == 0) {
        float v0 = sdot[lane], v1 = sdot[lane + 32];
        float mn = fminf(v0, v1), mx = fmaxf(v0, v1);
#pragma unroll
        for (int off = 16; off; off >>= 1) {
            mn = fminf(mn, __shfl_xor_sync(0xffffffffu, mn, off));
            mx = fmaxf(mx, __shfl_xor_sync(0xffffffffu, mx, off));
        }
        if (lane == 0) {
            atomicMin(&g_mnk[b_own], enc(mn));
            atomicMax(&g_mxk[b_own], enc(mx));
        }
    }
    // epilogue ticket: 16th block of each batch writes outputs + resets
    __syncthreads();
    if (t == 0) { __threadfence(); sh_tk = atomicAdd(&c_ep[b_own].v, 1u); }
    __syncthreads();
    if (sh_tk == 15u) {
        __threadfence();
        const float mn = dec(g_mnk[b_own]);
        const float mx = dec(g_mxk[b_own]);
        const float inv = 1.0f / (mx - mn);
#pragma unroll
        for (int i = 0; i < 2; ++i) {
            const int idx = t + i * NTHR;
            const float z = ((g_dot[b_own][idx] - mn) * inv - 0.65f) / 0.15f;
            out[b_own * HW + idx] = 1.0f / (1.0f + __expf(-z));
        }
        __syncthreads();
        if (t == 0) {
            g_mnk[b_own] = 0xFFFFFFFFu;     // reset per-batch state
            g_mxk[b_own] = 0u;
            c_ep[b_own].v = 0u;
            __threadfence();
            unsigned old = atomicAdd(&c_fin.v, 1u);
            if (old == 7u) {                // 8th winner: reset shared counters
#pragma unroll
                for (int i = 0; i < 8; ++i) c_cs[i].v = 0u;
#pragma unroll
                for (int i = 0; i < 4; ++i) { c_xr[i].v = 0u; c_ks[i].v = 0u; }
                c_xs.v = 0u; c_wp.v = 0u; c_up.v = 0u; c_fin.v = 0u;
                __threadfence();
            }
        }
    }
}

// ---------------------------------------------------------------------------
extern "C" void kernel_launch(void* const* d_in, const int* in_sizes, int n_in,
                              void* d_out, int out_size) {
    const float* x      = (const float*)d_in[0];
    const float* conv_w = (const float*)d_in[1];
    const float* conv_b = (const float*)d_in[2];
    const float* q_w    = (const float*)d_in[3];
    // d_in[4] = q_b: per-batch constant, cancels in min/max normalization.
    const float* k_w    = (const float*)d_in[5];
    const float* k_b    = (const float*)d_in[6];
    float* out = (float*)d_out;

    cudaFuncSetAttribute(fused_kernel,
                         cudaFuncAttributeMaxDynamicSharedMemorySize,
                         DYN_BYTES);
    fused_kernel<<<NBLK, NTHR, DYN_BYTES>>>(x, conv_w, conv_b, q_w, k_w, k_b, out);
}